// round 16
// baseline (speedup 1.0000x reference)
#include <cuda_runtime.h>
#include <cuda_bf16.h>
#include <cuda_fp16.h>
#include <cstdint>
#include <math.h>

// Problem constants
#define TOK   4096          // B*S
#define DM    1024          // d_model
#define D3    3072          // 3*d_model
#define NHEAD 16
#define DH    64
#define DFF   4096
#define NEXP  8
#define SEQ   1024
#define NB    4
#define TOTROWS (2*TOK)     // packed expert rows (top-2)

// ============================ scratch globals ============================
__device__ __align__(16) __half g_projh[(size_t)TOK * DM];
__device__ __align__(16) __half g_Yh[(size_t)TOTROWS * DM];
__device__ __align__(16) __half g_qkvh[(size_t)TOK * D3];
__device__ __align__(16) __half g_srch[(size_t)TOK * DM];
__device__ __align__(16) __half g_attnh[(size_t)TOK * DM];
__device__ __align__(16) __half g_wqkv[(size_t)D3 * DM];
__device__ __align__(16) __half g_wo[(size_t)DM * DM];
__device__ __align__(16) __half g_x1h[(size_t)TOK * DM];
__device__ __align__(16) __half g_w1h[(size_t)NEXP * DM * DFF];   // [e][K][N] (native)
__device__ __align__(16) __half g_w2h[(size_t)NEXP * DFF * DM];   // [e][K][N] (native)
__device__ __align__(16) __half g_Hh[(size_t)TOTROWS * DFF];

__device__ int   d_count[NEXP];
__device__ float d_Psum[NEXP];
__device__ int   d_list[NEXP * TOK];
__device__ int   d_slot[TOK * 2];
__device__ float d_gate[TOK * 2];

// ============================ PTX helpers (sm_80-level only) =================
__device__ __forceinline__ uint32_t smem_u32(const void* p) {
    uint32_t a;
    asm("{ .reg .u64 t; cvta.to.shared.u64 t, %1; cvt.u32.u64 %0, t; }"
        : "=r"(a) : "l"(p));
    return a;
}
__device__ __forceinline__ void cp16(uint32_t dst, const void* src, int sz) {
    asm volatile("cp.async.cg.shared.global [%0], [%1], 16, %2;"
                 :: "r"(dst), "l"(src), "r"(sz) : "memory");
}
#define CP_COMMIT() asm volatile("cp.async.commit_group;" ::: "memory")
template<int N_>
__device__ __forceinline__ void cp_wait() {
    asm volatile("cp.async.wait_group %0;" :: "n"(N_) : "memory");
}
__device__ __forceinline__ void ldsm4(uint32_t* r, uint32_t addr) {
    asm volatile("ldmatrix.sync.aligned.m8n8.x4.shared.b16 {%0,%1,%2,%3}, [%4];"
                 : "=r"(r[0]), "=r"(r[1]), "=r"(r[2]), "=r"(r[3]) : "r"(addr));
}
__device__ __forceinline__ void ldsm4t(uint32_t* r, uint32_t addr) {
    asm volatile("ldmatrix.sync.aligned.m8n8.x4.trans.shared.b16 {%0,%1,%2,%3}, [%4];"
                 : "=r"(r[0]), "=r"(r[1]), "=r"(r[2]), "=r"(r[3]) : "r"(addr));
}
__device__ __forceinline__ void mma16816h(float* c, const uint32_t* a, const uint32_t* b) {
    asm volatile("mma.sync.aligned.m16n8k16.row.col.f32.f16.f16.f32 "
                 "{%0,%1,%2,%3}, {%4,%5,%6,%7}, {%8,%9}, {%0,%1,%2,%3};"
                 : "+f"(c[0]), "+f"(c[1]), "+f"(c[2]), "+f"(c[3])
                 : "r"(a[0]), "r"(a[1]), "r"(a[2]), "r"(a[3]),
                   "r"(b[0]), "r"(b[1]));
}

// ============================ unified fp16 GEMM (single-term, BK=64) =========
// MODE 1: expert gather + relu + fp16 out. MODE 2: expert offset rows, fp16 out.
// MODE 3: dense fp16 out.
// TRANSB 0: B is [N,K] row-major. TRANSB 1: B is [K,N] row-major (ldsm4t).
// Expert modes compute the row-offset prefix in-kernel from d_count.
#define BM 128
#define BN 128
#define MBK 64
#define HA_BYTES 16384
#define HSTG_BYTES 32768
#define HNSTG 3
#define HGEMM_SMEM (HNSTG * HSTG_BYTES)

template<int MODE, int TRANSB>
__global__ __launch_bounds__(256, 2) void hgemm(
    const __half* __restrict__ AH, const __half* __restrict__ BH,
    const float* __restrict__ biasBase,
    __half* __restrict__ CH,
    const int* __restrict__ counts, const int* __restrict__ listBase,
    int Mfix, int N, int K)
{
    extern __shared__ __half smh[];
    const int tid = threadIdx.x;
    const int lane = tid & 31, wid = tid >> 5;
    const int wm = wid & 3, wn = wid >> 2;
    const int g = lane >> 2, tig = lane & 3;
    const int m0 = blockIdx.y * BM, n0 = blockIdx.x * BN;
    const int e = blockIdx.z;

    int M = Mfix;
    const __half* bhp = BH;
    const float* bias = biasBase;
    const int* lst = nullptr;
    int arow0 = 0, crow0 = 0;
    if (MODE == 1 || MODE == 2) {
        M = counts[e];
        if (m0 >= M) return;
        int off = 0;
#pragma unroll
        for (int i = 0; i < NEXP; i++) off += (i < e) ? counts[i] : 0;
        bhp += (size_t)e * N * K;
        bias += (size_t)e * N;
        crow0 = off;
        if (MODE == 1) lst = listBase + e * TOK;
        else arow0 = off;
    }

    const uint32_t sb = smem_u32(smh);

    float acc[2][8][4];
#pragma unroll
    for (int mt = 0; mt < 2; mt++)
#pragma unroll
        for (int nt = 0; nt < 8; nt++)
#pragma unroll
            for (int i = 0; i < 4; i++) acc[mt][nt][i] = 0.0f;

    auto load_stage = [&](int st, int k0) {
        uint32_t sbase = sb + st * HSTG_BYTES;
#pragma unroll
        for (int i = 0; i < 8; i++) {
            int u = tid + i * 256;
            int isB = u >> 10;
            int idx = u & 1023;
            if (!isB) {
                int row = idx >> 3, seg = idx & 7;
                uint32_t dst = sbase + row * 128
                             + (uint32_t)((seg ^ (row & 7)) << 4);
                int gr = m0 + row;
                size_t arow; int sz;
                if (MODE == 3) {
                    arow = (size_t)gr; sz = 16;
                } else if (MODE == 1) {
                    bool ok = gr < M;
                    arow = ok ? (size_t)lst[gr] : 0; sz = ok ? 16 : 0;
                } else {
                    bool ok = gr < M;
                    arow = (size_t)(arow0 + (ok ? gr : 0)); sz = ok ? 16 : 0;
                }
                cp16(dst, AH + arow * (size_t)K + k0 + seg * 8, sz);
            } else if (!TRANSB) {
                int row = idx >> 3, seg = idx & 7;
                uint32_t dst = sbase + HA_BYTES + row * 128
                             + (uint32_t)((seg ^ (row & 7)) << 4);
                cp16(dst, bhp + (size_t)(n0 + row) * K + k0 + seg * 8, 16);
            } else {
                int row = idx >> 4, sn = idx & 15;      // row = k (0..63), sn = n/8
                uint32_t dst = sbase + HA_BYTES + row * 256
                             + (uint32_t)((sn & 8) << 4)
                             + (uint32_t)((((sn & 7) ^ (row & 7))) << 4);
                cp16(dst, bhp + (size_t)(k0 + row) * N + n0 + sn * 8, 16);
            }
        }
    };

    const int a_row_in = (lane & 15);
    const int a_seg_in = (lane >> 4);
    const int b_row_in = (lane & 7) + ((lane & 16) ? 8 : 0);
    const int b_seg_in = (lane & 8) ? 1 : 0;

    auto compute = [&](int st) {
        uint32_t sA = sb + st * HSTG_BYTES;
        uint32_t sB = sA + HA_BYTES;
#pragma unroll
        for (int ks = 0; ks < 4; ks++) {
            const int kseg = ks * 2;
            uint32_t ah[2][4];
#pragma unroll
            for (int mt = 0; mt < 2; mt++) {
                int row = wm * 32 + mt * 16 + a_row_in;
                int sl = kseg + a_seg_in;
                ldsm4(ah[mt], sA + row * 128 + ((sl ^ (row & 7)) << 4));
            }
#pragma unroll
            for (int ntp = 0; ntp < 4; ntp++) {
                uint32_t bh[4];
                if (!TRANSB) {
                    int row = wn * 64 + ntp * 16 + b_row_in;
                    int sl = kseg + b_seg_in;
                    ldsm4(bh, sB + row * 128 + ((sl ^ (row & 7)) << 4));
                } else {
                    int row = ks * 16 + (lane & 15);
                    int sn = wn * 8 + ntp * 2 + (lane >> 4);
                    ldsm4t(bh, sB + row * 256 + ((sn & 8) << 4)
                               + (((sn & 7) ^ (row & 7)) << 4));
                }
#pragma unroll
                for (int half = 0; half < 2; half++) {
                    int nt = ntp * 2 + half;
#pragma unroll
                    for (int mt = 0; mt < 2; mt++)
                        mma16816h(acc[mt][nt], ah[mt], bh + half * 2);
                }
            }
        }
    };

    const int nk = K / MBK;
    load_stage(0, 0);
    CP_COMMIT();
    load_stage(1, MBK);
    CP_COMMIT();
    for (int c = 0; c < nk; c++) {
        cp_wait<1>();
        __syncthreads();
        compute(c % HNSTG);
        int cn = c + 2;
        if (cn < nk) load_stage(cn % HNSTG, cn * MBK);
        CP_COMMIT();
    }

#pragma unroll
    for (int nt = 0; nt < 8; nt++) {
        int col = n0 + wn * 64 + nt * 8 + 2 * tig;
        float b0 = bias[col], b1 = bias[col + 1];
#pragma unroll
        for (int mt = 0; mt < 2; mt++) {
            int r0 = m0 + wm * 32 + mt * 16 + g;
            float* c = acc[mt][nt];
#pragma unroll
            for (int hh = 0; hh < 2; hh++) {
                int r = r0 + hh * 8;
                if (MODE == 3 || r < M) {
                    float v0 = c[hh * 2 + 0] + b0;
                    float v1 = c[hh * 2 + 1] + b1;
                    if (MODE == 1) { v0 = fmaxf(v0, 0.0f); v1 = fmaxf(v1, 0.0f); }
                    size_t o = (size_t)(crow0 + r) * N + col;
                    *(__half2*)(CH + o) = __halves2half2(
                        __float2half_rn(v0), __float2half_rn(v1));
                }
            }
        }
    }
}

// ============================ flash attention (64 q-rows, R14 proven) ========
#define FA_Q_BYTES 8192
#define FA_KV_BYTES 16384
#define FA_SMEM (FA_Q_BYTES + 2 * FA_KV_BYTES)

__global__ __launch_bounds__(128) void fa_kernel(
    const __half* __restrict__ qkv, __half* __restrict__ oh)
{
    extern __shared__ __half fsm[];
    const uint32_t sQ = smem_u32(fsm);
    const uint32_t sK = sQ + FA_Q_BYTES;
    const uint32_t sV = sK + FA_KV_BYTES;

    const int bh = blockIdx.x;
    const int b = bh >> 4, h = bh & 15;
    const int qt = blockIdx.y;
    const int tid = threadIdx.x;
    const int lane = tid & 31, w = tid >> 5;
    const int g = lane >> 2, tig = lane & 3;
    const int hoff = h * DH;
    const size_t tq0 = (size_t)(b * SEQ + qt * 64);

    for (int i = tid; i < 512; i += 128) {
        int row = i >> 3, seg = i & 7;
        uint32_t dst = sQ + row * 128 + (uint32_t)((seg ^ (row & 7)) << 4);
        cp16(dst, qkv + (tq0 + row) * D3 + hoff + seg * 8, 16);
    }
    CP_COMMIT();
    cp_wait<0>();
    __syncthreads();

    uint32_t qa[4][4];
    {
        int row = w * 16 + (lane & 15);
        uint32_t base = sQ + row * 128;
#pragma unroll
        for (int ks = 0; ks < 4; ks++) {
            int sl = ks * 2 + (lane >> 4);
            ldsm4(qa[ks], base + ((sl ^ (row & 7)) << 4));
        }
    }

    const int b_row_in = (lane & 7) + ((lane & 16) ? 8 : 0);
    const int b_seg_in = (lane & 8) ? 1 : 0;

    float o[8][4];
#pragma unroll
    for (int dt = 0; dt < 8; dt++)
#pragma unroll
        for (int i = 0; i < 4; i++) o[dt][i] = 0.0f;
    float m0 = -1e30f, m1 = -1e30f, l0 = 0.0f, l1 = 0.0f;

    for (int kt = 0; kt < 8; kt++) {
        __syncthreads();
        const size_t tk0 = (size_t)(b * SEQ + kt * 128);
        for (int i = tid; i < 1024; i += 128) {
            int row = i >> 3, seg = i & 7;
            uint32_t sw = (uint32_t)((seg ^ (row & 7)) << 4);
            cp16(sK + row * 128 + sw, qkv + (tk0 + row) * D3 + DM + hoff + seg * 8, 16);
            cp16(sV + row * 128 + sw, qkv + (tk0 + row) * D3 + 2 * DM + hoff + seg * 8, 16);
        }
        CP_COMMIT();
        cp_wait<0>();
        __syncthreads();

        float sc[16][4];
#pragma unroll
        for (int nt = 0; nt < 16; nt++)
#pragma unroll
            for (int i = 0; i < 4; i++) sc[nt][i] = 0.0f;
#pragma unroll
        for (int ks = 0; ks < 4; ks++) {
#pragma unroll
            for (int ntp = 0; ntp < 8; ntp++) {
                int row = ntp * 16 + b_row_in;
                int sl = ks * 2 + b_seg_in;
                uint32_t kb[4];
                ldsm4(kb, sK + row * 128 + ((sl ^ (row & 7)) << 4));
                mma16816h(sc[ntp * 2 + 0], qa[ks], kb + 0);
                mma16816h(sc[ntp * 2 + 1], qa[ks], kb + 2);
            }
        }

        float mx0 = -1e30f, mx1 = -1e30f;
#pragma unroll
        for (int nt = 0; nt < 16; nt++) {
            mx0 = fmaxf(mx0, fmaxf(sc[nt][0], sc[nt][1]));
            mx1 = fmaxf(mx1, fmaxf(sc[nt][2], sc[nt][3]));
        }
        mx0 = fmaxf(mx0, __shfl_xor_sync(0xffffffffu, mx0, 1));
        mx0 = fmaxf(mx0, __shfl_xor_sync(0xffffffffu, mx0, 2));
        mx1 = fmaxf(mx1, __shfl_xor_sync(0xffffffffu, mx1, 1));
        mx1 = fmaxf(mx1, __shfl_xor_sync(0xffffffffu, mx1, 2));
        float m0n = fmaxf(m0, mx0 * 0.125f);
        float m1n = fmaxf(m1, mx1 * 0.125f);
        float f0 = __expf(m0 - m0n);
        float f1 = __expf(m1 - m1n);
        m0 = m0n; m1 = m1n;
        l0 *= f0; l1 *= f1;
#pragma unroll
        for (int dt = 0; dt < 8; dt++) {
            o[dt][0] *= f0; o[dt][1] *= f0;
            o[dt][2] *= f1; o[dt][3] *= f1;
        }

#pragma unroll
        for (int kk = 0; kk < 8; kk++) {
            float p00 = __expf(sc[2 * kk][0] * 0.125f - m0);
            float p01 = __expf(sc[2 * kk][1] * 0.125f - m0);
            float p02 = __expf(sc[2 * kk][2] * 0.125f - m1);
            float p03 = __expf(sc[2 * kk][3] * 0.125f - m1);
            float p10 = __expf(sc[2 * kk + 1][0] * 0.125f - m0);
            float p11 = __expf(sc[2 * kk + 1][1] * 0.125f - m0);
            float p12 = __expf(sc[2 * kk + 1][2] * 0.125f - m1);
            float p13 = __expf(sc[2 * kk + 1][3] * 0.125f - m1);
            l0 += p00 + p01 + p10 + p11;
            l1 += p02 + p03 + p12 + p13;
            uint32_t pa[4];
            __half2 h0 = __halves2half2(__float2half_rn(p00), __float2half_rn(p01));
            __half2 h1 = __halves2half2(__float2half_rn(p02), __float2half_rn(p03));
            __half2 h2 = __halves2half2(__float2half_rn(p10), __float2half_rn(p11));
            __half2 h3 = __halves2half2(__float2half_rn(p12), __float2half_rn(p13));
            pa[0] = *(uint32_t*)&h0;
            pa[1] = *(uint32_t*)&h1;
            pa[2] = *(uint32_t*)&h2;
            pa[3] = *(uint32_t*)&h3;
#pragma unroll
            for (int dp = 0; dp < 4; dp++) {
                int row = kk * 16 + (lane & 15);
                int seg = dp * 2 + (lane >> 4);
                uint32_t vb[4];
                ldsm4t(vb, sV + row * 128 + ((seg ^ (row & 7)) << 4));
                mma16816h(o[dp * 2 + 0], pa, vb + 0);
                mma16816h(o[dp * 2 + 1], pa, vb + 2);
            }
        }
    }

    l0 += __shfl_xor_sync(0xffffffffu, l0, 1);
    l0 += __shfl_xor_sync(0xffffffffu, l0, 2);
    l1 += __shfl_xor_sync(0xffffffffu, l1, 1);
    l1 += __shfl_xor_sync(0xffffffffu, l1, 2);
    float inv0 = 1.0f / l0, inv1 = 1.0f / l1;

    size_t r0 = tq0 + w * 16 + g;
    size_t r1 = r0 + 8;
#pragma unroll
    for (int dt = 0; dt < 8; dt++) {
        int col = hoff + dt * 8 + 2 * tig;
        *(__half2*)(oh + r0 * DM + col) = __halves2half2(
            __float2half_rn(o[dt][0] * inv0), __float2half_rn(o[dt][1] * inv0));
        *(__half2*)(oh + r1 * DM + col) = __halves2half2(
            __float2half_rn(o[dt][2] * inv1), __float2half_rn(o[dt][3] * inv1));
    }
}

// ============================ small kernels ============================
__global__ void init_kernel() {
    int i = threadIdx.x;
    if (i < NEXP) { d_count[i] = 0; d_Psum[i] = 0.0f; }
}

// load-balance loss only (runs at end)
__global__ void lb_kernel(float* __restrict__ out, int out_size) {
    if (threadIdx.x == 0) {
        float lb = 0.f;
#pragma unroll
        for (int e = 0; e < NEXP; e++) {
            float f = (float)d_count[e] / (float)(TOK * 2);
            float P = d_Psum[e] / (float)TOK;
            lb += f * P;
        }
        if (out_size > TOK * DM) out[out_size - 1] = (float)NEXP * lb;
    }
}

// two-tensor fp32 -> fp16 conversion in one launch
__global__ __launch_bounds__(256) void cvt2_h_kernel(
    const float* __restrict__ xa, __half* __restrict__ ha, int n4a,
    const float* __restrict__ xb, __half* __restrict__ hb, int n4b)
{
    int i = blockIdx.x * 256 + threadIdx.x;
    const float* x; __half* h;
    if (i < n4a) { x = xa; h = ha; }
    else { i -= n4a; if (i >= n4b) return; x = xb; h = hb; }
    float4 v = ((const float4*)x)[i];
    __half hv[4] = {__float2half_rn(v.x), __float2half_rn(v.y),
                    __float2half_rn(v.z), __float2half_rn(v.w)};
    *(uint2*)(h + i * 4) = *(uint2*)hv;
}

__global__ __launch_bounds__(256) void cvt_h_kernel(
    const float* __restrict__ x, __half* __restrict__ h, int n4)
{
    int i = blockIdx.x * 256 + threadIdx.x;
    if (i >= n4) return;
    float4 v = ((const float4*)x)[i];
    __half hv[4] = {__float2half_rn(v.x), __float2half_rn(v.y),
                    __float2half_rn(v.z), __float2half_rn(v.w)};
    *(uint2*)(h + i * 4) = *(uint2*)hv;
}

// ============================ fused add + LN + router ============================
__device__ __forceinline__ float blk_sum(float v, float* red) {
    int tid = threadIdx.x;
    red[tid] = v;
    __syncthreads();
#pragma unroll
    for (int s = 128; s > 0; s >>= 1) {
        if (tid < s) red[tid] += red[tid + s];
        __syncthreads();
    }
    float r = red[0];
    __syncthreads();
    return r;
}

__global__ __launch_bounds__(256) void add_ln_router_kernel(
    const float* __restrict__ a, const __half* __restrict__ bp,
    const float* __restrict__ g, const float* __restrict__ bb,
    const float* __restrict__ rw, const float* __restrict__ rb,
    __half* __restrict__ oh)
{
    __shared__ float red[256];
    __shared__ float ys[DM];
    __shared__ float logits[NEXP];
    size_t t = blockIdx.x;
    int tid = threadIdx.x;
    int w = tid >> 5, lane = tid & 31;
    float v[4];
    float s = 0.f;
#pragma unroll
    for (int i = 0; i < 4; i++) {
        int d = tid + i * 256;
        v[i] = a[t * DM + d] + __half2float(bp[t * DM + d]);
        s += v[i];
    }
    float mu = blk_sum(s, red) * (1.0f / DM);
    float sq = 0.f;
#pragma unroll
    for (int i = 0; i < 4; i++) { float c = v[i] - mu; sq += c * c; }
    float var = blk_sum(sq, red) * (1.0f / DM);
    float rstd = rsqrtf(var + 1e-5f);
#pragma unroll
    for (int i = 0; i < 4; i++) {
        int d = tid + i * 256;
        float y = (v[i] - mu) * rstd * g[d] + bb[d];
        oh[t * DM + d] = __float2half_rn(y);
        ys[d] = y;
    }
    __syncthreads();

    if (w < NEXP) {
        float sl = 0.f;
        for (int k = lane; k < DM; k += 32)
            sl += ys[k] * rw[(size_t)w * DM + k];
#pragma unroll
        for (int off = 16; off; off >>= 1) sl += __shfl_xor_sync(0xffffffffu, sl, off);
        if (lane == 0) logits[w] = sl + rb[w];
    }
    __syncthreads();
    if (tid == 0) {
        float p[NEXP];
        float mx = logits[0];
#pragma unroll
        for (int e = 1; e < NEXP; e++) mx = fmaxf(mx, logits[e]);
        float sum = 0.f;
#pragma unroll
        for (int e = 0; e < NEXP; e++) { p[e] = expf(logits[e] - mx); sum += p[e]; }
        float invs = 1.0f / sum;
#pragma unroll
        for (int e = 0; e < NEXP; e++) {
            p[e] *= invs;
            atomicAdd(&d_Psum[e], p[e]);
        }
        int i0 = 0;
#pragma unroll
        for (int e = 1; e < NEXP; e++) if (p[e] > p[i0]) i0 = e;
        int i1 = (i0 == 0) ? 1 : 0;
#pragma unroll
        for (int e = 0; e < NEXP; e++) if (e != i0 && p[e] > p[i1]) i1 = e;
        float gsum = p[i0] + p[i1];

        int pos0 = atomicAdd(&d_count[i0], 1);
        d_list[i0 * TOK + pos0] = (int)t;
        d_slot[t * 2 + 0] = i0 * TOK + pos0;
        d_gate[t * 2 + 0] = p[i0] / gsum;

        int pos1 = atomicAdd(&d_count[i1], 1);
        d_list[i1 * TOK + pos1] = (int)t;
        d_slot[t * 2 + 1] = i1 * TOK + pos1;
        d_gate[t * 2 + 1] = p[i1] / gsum;
    }
}

__global__ __launch_bounds__(256) void combine_ln_kernel(
    const __half* __restrict__ Y, const __half* __restrict__ x1,
    const float* __restrict__ g, const float* __restrict__ bb,
    float* __restrict__ out)
{
    __shared__ float red[256];
    __shared__ int soff[NEXP];
    size_t t = blockIdx.x;
    int tid = threadIdx.x;
    if (tid == 0) {
        int a = 0;
#pragma unroll
        for (int e = 0; e < NEXP; e++) { soff[e] = a; a += d_count[e]; }
    }
    __syncthreads();
    int sl0 = d_slot[t * 2 + 0], sl1 = d_slot[t * 2 + 1];
    size_t r0 = (size_t)soff[sl0 / TOK] + (sl0 % TOK);
    size_t r1 = (size_t)soff[sl1 / TOK] + (sl1 % TOK);
    float g0 = d_gate[t * 2 + 0], g1 = d_gate[t * 2 + 1];
    float v[4];
    float s = 0.f;
#pragma unroll
    for (int i = 0; i < 4; i++) {
        int d = tid + i * 256;
        float y = g0 * __half2float(Y[r0 * DM + d]) + g1 * __half2float(Y[r1 * DM + d]);
        v[i] = __half2float(x1[t * DM + d]) + y;
        s += v[i];
    }
    float mu = blk_sum(s, red) * (1.0f / DM);
    float sq = 0.f;
#pragma unroll
    for (int i = 0; i < 4; i++) { float c = v[i] - mu; sq += c * c; }
    float var = blk_sum(sq, red) * (1.0f / DM);
    float rstd = rsqrtf(var + 1e-5f);
#pragma unroll
    for (int i = 0; i < 4; i++) {
        int d = tid + i * 256;
        out[t * DM + d] = (v[i] - mu) * rstd * g[d] + bb[d];
    }
}

// ============================ launch ============================
extern "C" void kernel_launch(void* const* d_in, const int* in_sizes, int n_in,
                              void* d_out, int out_size)
{
    const float* src   = (const float*)d_in[0];
    const float* in_w  = (const float*)d_in[1];
    const float* in_b  = (const float*)d_in[2];
    const float* out_w = (const float*)d_in[3];
    const float* out_b = (const float*)d_in[4];
    const float* ln1g  = (const float*)d_in[5];
    const float* ln1b  = (const float*)d_in[6];
    const float* rw    = (const float*)d_in[7];
    const float* rb    = (const float*)d_in[8];
    const float* w1    = (const float*)d_in[9];
    const float* b1    = (const float*)d_in[10];
    const float* w2    = (const float*)d_in[11];
    const float* b2    = (const float*)d_in[12];
    const float* ln2g  = (const float*)d_in[13];
    const float* ln2b  = (const float*)d_in[14];
    float* out = (float*)d_out;

#define GETP(T, sym) ({ void* _p; cudaGetSymbolAddress(&_p, sym); (T*)_p; })
    __half* projh = GETP(__half, g_projh);
    __half* Yh    = GETP(__half, g_Yh);
    __half* qkvh  = GETP(__half, g_qkvh);
    __half* srch  = GETP(__half, g_srch);
    __half* attnh = GETP(__half, g_attnh);
    __half* wqkv  = GETP(__half, g_wqkv);
    __half* wo    = GETP(__half, g_wo);
    __half* x1h = GETP(__half, g_x1h);
    __half* w1h = GETP(__half, g_w1h);
    __half* w2h = GETP(__half, g_w2h);
    __half* Hh  = GETP(__half, g_Hh);
    int* cnt  = GETP(int, d_count);
    int* list = GETP(int, d_list);

    static cudaStream_t s_side = nullptr;
    static cudaEvent_t ev_fork, ev_wo, ev_w1, ev_w2;
    static bool attr_done = false;
    if (!attr_done) {
        cudaFuncSetAttribute((hgemm<1,1>), cudaFuncAttributeMaxDynamicSharedMemorySize, HGEMM_SMEM);
        cudaFuncSetAttribute((hgemm<2,1>), cudaFuncAttributeMaxDynamicSharedMemorySize, HGEMM_SMEM);
        cudaFuncSetAttribute((hgemm<3,0>), cudaFuncAttributeMaxDynamicSharedMemorySize, HGEMM_SMEM);
        cudaFuncSetAttribute(fa_kernel, cudaFuncAttributeMaxDynamicSharedMemorySize, FA_SMEM);
        cudaStreamCreateWithFlags(&s_side, cudaStreamNonBlocking);
        cudaEventCreateWithFlags(&ev_fork, cudaEventDisableTiming);
        cudaEventCreateWithFlags(&ev_wo, cudaEventDisableTiming);
        cudaEventCreateWithFlags(&ev_w1, cudaEventDisableTiming);
        cudaEventCreateWithFlags(&ev_w2, cudaEventDisableTiming);
        attr_done = true;
    }

    init_kernel<<<1, 32>>>();

    // fused conversion: src + wqkv in one launch
    {
        int n4a = TOK * DM / 4, n4b = D3 * DM / 4;
        cvt2_h_kernel<<<(n4a + n4b + 255) / 256, 256>>>(src, srch, n4a, in_w, wqkv, n4b);
    }

    // side stream: straight fp16 copies
    cudaEventRecord(ev_fork, 0);
    cudaStreamWaitEvent(s_side, ev_fork, 0);
    cvt_h_kernel<<<(DM * DM / 4 + 255) / 256, 256, 0, s_side>>>(out_w, wo, DM * DM / 4);
    cudaEventRecord(ev_wo, s_side);
    cvt_h_kernel<<<(NEXP * DM * DFF / 4 + 255) / 256, 256, 0, s_side>>>(w1, w1h, NEXP * DM * DFF / 4);
    cudaEventRecord(ev_w1, s_side);
    cvt_h_kernel<<<(NEXP * DFF * DM / 4 + 255) / 256, 256, 0, s_side>>>(w2, w2h, NEXP * DFF * DM / 4);
    cudaEventRecord(ev_w2, s_side);

    // QKV = src @ in_w^T + b  (fp16 out, B = [N,K])
    hgemm<3,0><<<dim3(D3 / BN, TOK / BM), 256, HGEMM_SMEM>>>(
        srch, wqkv, in_b, qkvh, nullptr, nullptr, TOK, D3, DM);

    // flash attention (64 q-rows/block, single buffer — proven config)
    fa_kernel<<<dim3(NB * NHEAD, SEQ / 64), 128, FA_SMEM>>>(qkvh, attnh);

    // proj = attn @ out_w^T + b  (fp16 out, B = [N,K])
    cudaStreamWaitEvent(0, ev_wo, 0);
    hgemm<3,0><<<dim3(DM / BN, TOK / BM), 256, HGEMM_SMEM>>>(
        attnh, wo, out_b, projh, nullptr, nullptr, TOK, DM, DM);

    // x1 = LN(src + proj) + fused router
    add_ln_router_kernel<<<TOK, 256>>>(src, projh, ln1g, ln1b, rw, rb, x1h);

    // H = relu(gather(x1) @ w1 + b1)  (offsets computed in-kernel)
    cudaStreamWaitEvent(0, ev_w1, 0);
    hgemm<1,1><<<dim3(DFF / BN, TOK / BM, NEXP), 256, HGEMM_SMEM>>>(
        x1h, w1h, b1, Hh, cnt, list, 0, DFF, DM);
    // Y = H @ w2 + b2
    cudaStreamWaitEvent(0, ev_w2, 0);
    hgemm<2,1><<<dim3(DM / BN, TOK / BM, NEXP), 256, HGEMM_SMEM>>>(
        Hh, w2h, b2, Yh, cnt, nullptr, 0, DM, DFF);

    combine_ln_kernel<<<TOK, 256>>>(Yh, x1h, ln2g, ln2b, out);
    lb_kernel<<<1, 32>>>(out, out_size);
}

// round 17
// speedup vs baseline: 1.4742x; 1.4742x over previous
#include <cuda_runtime.h>
#include <cuda_bf16.h>
#include <cuda_fp16.h>
#include <cstdint>
#include <math.h>

// Problem constants
#define TOK   4096          // B*S
#define DM    1024          // d_model
#define D3    3072          // 3*d_model
#define NHEAD 16
#define DH    64
#define DFF   4096
#define NEXP  8
#define SEQ   1024
#define NB    4
#define TOTROWS (2*TOK)     // packed expert rows (top-2)

// ============================ scratch globals ============================
__device__ __align__(16) __half g_projh[(size_t)TOK * DM];
__device__ __align__(16) __half g_Yh[(size_t)TOTROWS * DM];
__device__ __align__(16) __half g_qkvh[(size_t)TOK * D3];
__device__ __align__(16) __half g_srch[(size_t)TOK * DM];
__device__ __align__(16) __half g_attnh[(size_t)TOK * DM];
__device__ __align__(16) __half g_wqkv[(size_t)D3 * DM];
__device__ __align__(16) __half g_wo[(size_t)DM * DM];
__device__ __align__(16) __half g_x1h[(size_t)TOK * DM];
__device__ __align__(16) __half g_w1h[(size_t)NEXP * DM * DFF];   // [e][K][N] (native)
__device__ __align__(16) __half g_w2h[(size_t)NEXP * DFF * DM];   // [e][K][N] (native)
__device__ __align__(16) __half g_Hh[(size_t)TOTROWS * DFF];

__device__ int   d_count[NEXP];
__device__ float d_Psum[NEXP];
__device__ int   d_list[NEXP * TOK];
__device__ int   d_slot[TOK * 2];
__device__ float d_gate[TOK * 2];

// ============================ PTX helpers (sm_80-level only) =================
__device__ __forceinline__ uint32_t smem_u32(const void* p) {
    uint32_t a;
    asm("{ .reg .u64 t; cvta.to.shared.u64 t, %1; cvt.u32.u64 %0, t; }"
        : "=r"(a) : "l"(p));
    return a;
}
__device__ __forceinline__ void cp16(uint32_t dst, const void* src, int sz) {
    asm volatile("cp.async.cg.shared.global [%0], [%1], 16, %2;"
                 :: "r"(dst), "l"(src), "r"(sz) : "memory");
}
#define CP_COMMIT() asm volatile("cp.async.commit_group;" ::: "memory")
template<int N_>
__device__ __forceinline__ void cp_wait() {
    asm volatile("cp.async.wait_group %0;" :: "n"(N_) : "memory");
}
__device__ __forceinline__ void ldsm4(uint32_t* r, uint32_t addr) {
    asm volatile("ldmatrix.sync.aligned.m8n8.x4.shared.b16 {%0,%1,%2,%3}, [%4];"
                 : "=r"(r[0]), "=r"(r[1]), "=r"(r[2]), "=r"(r[3]) : "r"(addr));
}
__device__ __forceinline__ void ldsm4t(uint32_t* r, uint32_t addr) {
    asm volatile("ldmatrix.sync.aligned.m8n8.x4.trans.shared.b16 {%0,%1,%2,%3}, [%4];"
                 : "=r"(r[0]), "=r"(r[1]), "=r"(r[2]), "=r"(r[3]) : "r"(addr));
}
__device__ __forceinline__ void mma16816h(float* c, const uint32_t* a, const uint32_t* b) {
    asm volatile("mma.sync.aligned.m16n8k16.row.col.f32.f16.f16.f32 "
                 "{%0,%1,%2,%3}, {%4,%5,%6,%7}, {%8,%9}, {%0,%1,%2,%3};"
                 : "+f"(c[0]), "+f"(c[1]), "+f"(c[2]), "+f"(c[3])
                 : "r"(a[0]), "r"(a[1]), "r"(a[2]), "r"(a[3]),
                   "r"(b[0]), "r"(b[1]));
}

// ============================ unified fp16 GEMM (single-term, BK=64) =========
// MODE 1: expert gather + relu + fp16 out. MODE 2: expert offset rows, fp16 out.
// MODE 3: dense fp16 out.
// TRANSB 0: B is [N,K] row-major. TRANSB 1: B is [K,N] row-major (ldsm4t).
// Expert modes compute the row-offset prefix in-kernel from d_count.
#define BM 128
#define BN 128
#define MBK 64
#define HA_BYTES 16384
#define HSTG_BYTES 32768
#define HNSTG 3
#define HGEMM_SMEM (HNSTG * HSTG_BYTES)

template<int MODE, int TRANSB>
__global__ __launch_bounds__(256, 2) void hgemm(
    const __half* __restrict__ AH, const __half* __restrict__ BH,
    const float* __restrict__ biasBase,
    __half* __restrict__ CH,
    const int* __restrict__ counts, const int* __restrict__ listBase,
    int Mfix, int N, int K)
{
    extern __shared__ __half smh[];
    const int tid = threadIdx.x;
    const int lane = tid & 31, wid = tid >> 5;
    const int wm = wid & 3, wn = wid >> 2;
    const int g = lane >> 2, tig = lane & 3;
    const int m0 = blockIdx.y * BM, n0 = blockIdx.x * BN;
    const int e = blockIdx.z;

    int M = Mfix;
    const __half* bhp = BH;
    const float* bias = biasBase;
    const int* lst = nullptr;
    int arow0 = 0, crow0 = 0;
    if (MODE == 1 || MODE == 2) {
        M = counts[e];
        if (m0 >= M) return;
        int off = 0;
#pragma unroll
        for (int i = 0; i < NEXP; i++) off += (i < e) ? counts[i] : 0;
        bhp += (size_t)e * N * K;
        bias += (size_t)e * N;
        crow0 = off;
        if (MODE == 1) lst = listBase + e * TOK;
        else arow0 = off;
    }

    const uint32_t sb = smem_u32(smh);

    float acc[2][8][4];
#pragma unroll
    for (int mt = 0; mt < 2; mt++)
#pragma unroll
        for (int nt = 0; nt < 8; nt++)
#pragma unroll
            for (int i = 0; i < 4; i++) acc[mt][nt][i] = 0.0f;

    auto load_stage = [&](int st, int k0) {
        uint32_t sbase = sb + st * HSTG_BYTES;
#pragma unroll
        for (int i = 0; i < 8; i++) {
            int u = tid + i * 256;
            int isB = u >> 10;
            int idx = u & 1023;
            if (!isB) {
                int row = idx >> 3, seg = idx & 7;
                uint32_t dst = sbase + row * 128
                             + (uint32_t)((seg ^ (row & 7)) << 4);
                int gr = m0 + row;
                size_t arow; int sz;
                if (MODE == 3) {
                    arow = (size_t)gr; sz = 16;
                } else if (MODE == 1) {
                    bool ok = gr < M;
                    arow = ok ? (size_t)lst[gr] : 0; sz = ok ? 16 : 0;
                } else {
                    bool ok = gr < M;
                    arow = (size_t)(arow0 + (ok ? gr : 0)); sz = ok ? 16 : 0;
                }
                cp16(dst, AH + arow * (size_t)K + k0 + seg * 8, sz);
            } else if (!TRANSB) {
                int row = idx >> 3, seg = idx & 7;
                uint32_t dst = sbase + HA_BYTES + row * 128
                             + (uint32_t)((seg ^ (row & 7)) << 4);
                cp16(dst, bhp + (size_t)(n0 + row) * K + k0 + seg * 8, 16);
            } else {
                int row = idx >> 4, sn = idx & 15;      // row = k (0..63), sn = n/8
                uint32_t dst = sbase + HA_BYTES + row * 256
                             + (uint32_t)((sn & 8) << 4)
                             + (uint32_t)((((sn & 7) ^ (row & 7))) << 4);
                cp16(dst, bhp + (size_t)(k0 + row) * N + n0 + sn * 8, 16);
            }
        }
    };

    const int a_row_in = (lane & 15);
    const int a_seg_in = (lane >> 4);
    const int b_row_in = (lane & 7) + ((lane & 16) ? 8 : 0);
    const int b_seg_in = (lane & 8) ? 1 : 0;

    auto compute = [&](int st) {
        uint32_t sA = sb + st * HSTG_BYTES;
        uint32_t sB = sA + HA_BYTES;
#pragma unroll
        for (int ks = 0; ks < 4; ks++) {
            const int kseg = ks * 2;
            uint32_t ah[2][4];
#pragma unroll
            for (int mt = 0; mt < 2; mt++) {
                int row = wm * 32 + mt * 16 + a_row_in;
                int sl = kseg + a_seg_in;
                ldsm4(ah[mt], sA + row * 128 + ((sl ^ (row & 7)) << 4));
            }
#pragma unroll
            for (int ntp = 0; ntp < 4; ntp++) {
                uint32_t bh[4];
                if (!TRANSB) {
                    int row = wn * 64 + ntp * 16 + b_row_in;
                    int sl = kseg + b_seg_in;
                    ldsm4(bh, sB + row * 128 + ((sl ^ (row & 7)) << 4));
                } else {
                    int row = ks * 16 + (lane & 15);
                    int sn = wn * 8 + ntp * 2 + (lane >> 4);
                    ldsm4t(bh, sB + row * 256 + ((sn & 8) << 4)
                               + (((sn & 7) ^ (row & 7)) << 4));
                }
#pragma unroll
                for (int half = 0; half < 2; half++) {
                    int nt = ntp * 2 + half;
#pragma unroll
                    for (int mt = 0; mt < 2; mt++)
                        mma16816h(acc[mt][nt], ah[mt], bh + half * 2);
                }
            }
        }
    };

    const int nk = K / MBK;
    load_stage(0, 0);
    CP_COMMIT();
    load_stage(1, MBK);
    CP_COMMIT();
    for (int c = 0; c < nk; c++) {
        cp_wait<1>();
        __syncthreads();
        compute(c % HNSTG);
        int cn = c + 2;
        if (cn < nk) load_stage(cn % HNSTG, cn * MBK);
        CP_COMMIT();
    }

#pragma unroll
    for (int nt = 0; nt < 8; nt++) {
        int col = n0 + wn * 64 + nt * 8 + 2 * tig;
        float b0 = bias[col], b1 = bias[col + 1];
#pragma unroll
        for (int mt = 0; mt < 2; mt++) {
            int r0 = m0 + wm * 32 + mt * 16 + g;
            float* c = acc[mt][nt];
#pragma unroll
            for (int hh = 0; hh < 2; hh++) {
                int r = r0 + hh * 8;
                if (MODE == 3 || r < M) {
                    float v0 = c[hh * 2 + 0] + b0;
                    float v1 = c[hh * 2 + 1] + b1;
                    if (MODE == 1) { v0 = fmaxf(v0, 0.0f); v1 = fmaxf(v1, 0.0f); }
                    size_t o = (size_t)(crow0 + r) * N + col;
                    *(__half2*)(CH + o) = __halves2half2(
                        __float2half_rn(v0), __float2half_rn(v1));
                }
            }
        }
    }
}

// ============================ flash attention (64 q-rows, R14 proven) ========
#define FA_Q_BYTES 8192
#define FA_KV_BYTES 16384
#define FA_SMEM (FA_Q_BYTES + 2 * FA_KV_BYTES)

__global__ __launch_bounds__(128) void fa_kernel(
    const __half* __restrict__ qkv, __half* __restrict__ oh)
{
    extern __shared__ __half fsm[];
    const uint32_t sQ = smem_u32(fsm);
    const uint32_t sK = sQ + FA_Q_BYTES;
    const uint32_t sV = sK + FA_KV_BYTES;

    const int bh = blockIdx.x;
    const int b = bh >> 4, h = bh & 15;
    const int qt = blockIdx.y;
    const int tid = threadIdx.x;
    const int lane = tid & 31, w = tid >> 5;
    const int g = lane >> 2, tig = lane & 3;
    const int hoff = h * DH;
    const size_t tq0 = (size_t)(b * SEQ + qt * 64);

    for (int i = tid; i < 512; i += 128) {
        int row = i >> 3, seg = i & 7;
        uint32_t dst = sQ + row * 128 + (uint32_t)((seg ^ (row & 7)) << 4);
        cp16(dst, qkv + (tq0 + row) * D3 + hoff + seg * 8, 16);
    }
    CP_COMMIT();
    cp_wait<0>();
    __syncthreads();

    uint32_t qa[4][4];
    {
        int row = w * 16 + (lane & 15);
        uint32_t base = sQ + row * 128;
#pragma unroll
        for (int ks = 0; ks < 4; ks++) {
            int sl = ks * 2 + (lane >> 4);
            ldsm4(qa[ks], base + ((sl ^ (row & 7)) << 4));
        }
    }

    const int b_row_in = (lane & 7) + ((lane & 16) ? 8 : 0);
    const int b_seg_in = (lane & 8) ? 1 : 0;

    float o[8][4];
#pragma unroll
    for (int dt = 0; dt < 8; dt++)
#pragma unroll
        for (int i = 0; i < 4; i++) o[dt][i] = 0.0f;
    float m0 = -1e30f, m1 = -1e30f, l0 = 0.0f, l1 = 0.0f;

    for (int kt = 0; kt < 8; kt++) {
        __syncthreads();
        const size_t tk0 = (size_t)(b * SEQ + kt * 128);
        for (int i = tid; i < 1024; i += 128) {
            int row = i >> 3, seg = i & 7;
            uint32_t sw = (uint32_t)((seg ^ (row & 7)) << 4);
            cp16(sK + row * 128 + sw, qkv + (tk0 + row) * D3 + DM + hoff + seg * 8, 16);
            cp16(sV + row * 128 + sw, qkv + (tk0 + row) * D3 + 2 * DM + hoff + seg * 8, 16);
        }
        CP_COMMIT();
        cp_wait<0>();
        __syncthreads();

        float sc[16][4];
#pragma unroll
        for (int nt = 0; nt < 16; nt++)
#pragma unroll
            for (int i = 0; i < 4; i++) sc[nt][i] = 0.0f;
#pragma unroll
        for (int ks = 0; ks < 4; ks++) {
#pragma unroll
            for (int ntp = 0; ntp < 8; ntp++) {
                int row = ntp * 16 + b_row_in;
                int sl = ks * 2 + b_seg_in;
                uint32_t kb[4];
                ldsm4(kb, sK + row * 128 + ((sl ^ (row & 7)) << 4));
                mma16816h(sc[ntp * 2 + 0], qa[ks], kb + 0);
                mma16816h(sc[ntp * 2 + 1], qa[ks], kb + 2);
            }
        }

        float mx0 = -1e30f, mx1 = -1e30f;
#pragma unroll
        for (int nt = 0; nt < 16; nt++) {
            mx0 = fmaxf(mx0, fmaxf(sc[nt][0], sc[nt][1]));
            mx1 = fmaxf(mx1, fmaxf(sc[nt][2], sc[nt][3]));
        }
        mx0 = fmaxf(mx0, __shfl_xor_sync(0xffffffffu, mx0, 1));
        mx0 = fmaxf(mx0, __shfl_xor_sync(0xffffffffu, mx0, 2));
        mx1 = fmaxf(mx1, __shfl_xor_sync(0xffffffffu, mx1, 1));
        mx1 = fmaxf(mx1, __shfl_xor_sync(0xffffffffu, mx1, 2));
        float m0n = fmaxf(m0, mx0 * 0.125f);
        float m1n = fmaxf(m1, mx1 * 0.125f);
        float f0 = __expf(m0 - m0n);
        float f1 = __expf(m1 - m1n);
        m0 = m0n; m1 = m1n;
        l0 *= f0; l1 *= f1;
#pragma unroll
        for (int dt = 0; dt < 8; dt++) {
            o[dt][0] *= f0; o[dt][1] *= f0;
            o[dt][2] *= f1; o[dt][3] *= f1;
        }

#pragma unroll
        for (int kk = 0; kk < 8; kk++) {
            float p00 = __expf(sc[2 * kk][0] * 0.125f - m0);
            float p01 = __expf(sc[2 * kk][1] * 0.125f - m0);
            float p02 = __expf(sc[2 * kk][2] * 0.125f - m1);
            float p03 = __expf(sc[2 * kk][3] * 0.125f - m1);
            float p10 = __expf(sc[2 * kk + 1][0] * 0.125f - m0);
            float p11 = __expf(sc[2 * kk + 1][1] * 0.125f - m0);
            float p12 = __expf(sc[2 * kk + 1][2] * 0.125f - m1);
            float p13 = __expf(sc[2 * kk + 1][3] * 0.125f - m1);
            l0 += p00 + p01 + p10 + p11;
            l1 += p02 + p03 + p12 + p13;
            uint32_t pa[4];
            __half2 h0 = __halves2half2(__float2half_rn(p00), __float2half_rn(p01));
            __half2 h1 = __halves2half2(__float2half_rn(p02), __float2half_rn(p03));
            __half2 h2 = __halves2half2(__float2half_rn(p10), __float2half_rn(p11));
            __half2 h3 = __halves2half2(__float2half_rn(p12), __float2half_rn(p13));
            pa[0] = *(uint32_t*)&h0;
            pa[1] = *(uint32_t*)&h1;
            pa[2] = *(uint32_t*)&h2;
            pa[3] = *(uint32_t*)&h3;
#pragma unroll
            for (int dp = 0; dp < 4; dp++) {
                int row = kk * 16 + (lane & 15);
                int seg = dp * 2 + (lane >> 4);
                uint32_t vb[4];
                ldsm4t(vb, sV + row * 128 + ((seg ^ (row & 7)) << 4));
                mma16816h(o[dp * 2 + 0], pa, vb + 0);
                mma16816h(o[dp * 2 + 1], pa, vb + 2);
            }
        }
    }

    l0 += __shfl_xor_sync(0xffffffffu, l0, 1);
    l0 += __shfl_xor_sync(0xffffffffu, l0, 2);
    l1 += __shfl_xor_sync(0xffffffffu, l1, 1);
    l1 += __shfl_xor_sync(0xffffffffu, l1, 2);
    float inv0 = 1.0f / l0, inv1 = 1.0f / l1;

    size_t r0 = tq0 + w * 16 + g;
    size_t r1 = r0 + 8;
#pragma unroll
    for (int dt = 0; dt < 8; dt++) {
        int col = hoff + dt * 8 + 2 * tig;
        *(__half2*)(oh + r0 * DM + col) = __halves2half2(
            __float2half_rn(o[dt][0] * inv0), __float2half_rn(o[dt][1] * inv0));
        *(__half2*)(oh + r1 * DM + col) = __halves2half2(
            __float2half_rn(o[dt][2] * inv1), __float2half_rn(o[dt][3] * inv1));
    }
}

// ============================ small kernels ============================
__global__ void init_kernel() {
    int i = threadIdx.x;
    if (i < NEXP) { d_count[i] = 0; d_Psum[i] = 0.0f; }
}

// load-balance loss only (runs at end)
__global__ void lb_kernel(float* __restrict__ out, int out_size) {
    if (threadIdx.x == 0) {
        float lb = 0.f;
#pragma unroll
        for (int e = 0; e < NEXP; e++) {
            float f = (float)d_count[e] / (float)(TOK * 2);
            float P = d_Psum[e] / (float)TOK;
            lb += f * P;
        }
        if (out_size > TOK * DM) out[out_size - 1] = (float)NEXP * lb;
    }
}

// two-tensor fp32 -> fp16 conversion in one launch
__global__ __launch_bounds__(256) void cvt2_h_kernel(
    const float* __restrict__ xa, __half* __restrict__ ha, int n4a,
    const float* __restrict__ xb, __half* __restrict__ hb, int n4b)
{
    int i = blockIdx.x * 256 + threadIdx.x;
    const float* x; __half* h;
    if (i < n4a) { x = xa; h = ha; }
    else { i -= n4a; if (i >= n4b) return; x = xb; h = hb; }
    float4 v = ((const float4*)x)[i];
    __half hv[4] = {__float2half_rn(v.x), __float2half_rn(v.y),
                    __float2half_rn(v.z), __float2half_rn(v.w)};
    *(uint2*)(h + i * 4) = *(uint2*)hv;
}

__global__ __launch_bounds__(256) void cvt_h_kernel(
    const float* __restrict__ x, __half* __restrict__ h, int n4)
{
    int i = blockIdx.x * 256 + threadIdx.x;
    if (i >= n4) return;
    float4 v = ((const float4*)x)[i];
    __half hv[4] = {__float2half_rn(v.x), __float2half_rn(v.y),
                    __float2half_rn(v.z), __float2half_rn(v.w)};
    *(uint2*)(h + i * 4) = *(uint2*)hv;
}

// ============================ fused add + LN + router ============================
__device__ __forceinline__ float blk_sum(float v, float* red) {
    int tid = threadIdx.x;
    red[tid] = v;
    __syncthreads();
#pragma unroll
    for (int s = 128; s > 0; s >>= 1) {
        if (tid < s) red[tid] += red[tid + s];
        __syncthreads();
    }
    float r = red[0];
    __syncthreads();
    return r;
}

__global__ __launch_bounds__(256) void add_ln_router_kernel(
    const float* __restrict__ a, const __half* __restrict__ bp,
    const float* __restrict__ g, const float* __restrict__ bb,
    const float* __restrict__ rw, const float* __restrict__ rb,
    __half* __restrict__ oh)
{
    __shared__ float red[256];
    __shared__ float ys[DM];
    __shared__ float logits[NEXP];
    size_t t = blockIdx.x;
    int tid = threadIdx.x;
    int w = tid >> 5, lane = tid & 31;
    float v[4];
    float s = 0.f;
#pragma unroll
    for (int i = 0; i < 4; i++) {
        int d = tid + i * 256;
        v[i] = a[t * DM + d] + __half2float(bp[t * DM + d]);
        s += v[i];
    }
    float mu = blk_sum(s, red) * (1.0f / DM);
    float sq = 0.f;
#pragma unroll
    for (int i = 0; i < 4; i++) { float c = v[i] - mu; sq += c * c; }
    float var = blk_sum(sq, red) * (1.0f / DM);
    float rstd = rsqrtf(var + 1e-5f);
#pragma unroll
    for (int i = 0; i < 4; i++) {
        int d = tid + i * 256;
        float y = (v[i] - mu) * rstd * g[d] + bb[d];
        oh[t * DM + d] = __float2half_rn(y);
        ys[d] = y;
    }
    __syncthreads();

    if (w < NEXP) {
        float sl = 0.f;
        for (int k = lane; k < DM; k += 32)
            sl += ys[k] * rw[(size_t)w * DM + k];
#pragma unroll
        for (int off = 16; off; off >>= 1) sl += __shfl_xor_sync(0xffffffffu, sl, off);
        if (lane == 0) logits[w] = sl + rb[w];
    }
    __syncthreads();
    if (tid == 0) {
        float p[NEXP];
        float mx = logits[0];
#pragma unroll
        for (int e = 1; e < NEXP; e++) mx = fmaxf(mx, logits[e]);
        float sum = 0.f;
#pragma unroll
        for (int e = 0; e < NEXP; e++) { p[e] = expf(logits[e] - mx); sum += p[e]; }
        float invs = 1.0f / sum;
#pragma unroll
        for (int e = 0; e < NEXP; e++) {
            p[e] *= invs;
            atomicAdd(&d_Psum[e], p[e]);
        }
        int i0 = 0;
#pragma unroll
        for (int e = 1; e < NEXP; e++) if (p[e] > p[i0]) i0 = e;
        int i1 = (i0 == 0) ? 1 : 0;
#pragma unroll
        for (int e = 0; e < NEXP; e++) if (e != i0 && p[e] > p[i1]) i1 = e;
        float gsum = p[i0] + p[i1];

        int pos0 = atomicAdd(&d_count[i0], 1);
        d_list[i0 * TOK + pos0] = (int)t;
        d_slot[t * 2 + 0] = i0 * TOK + pos0;
        d_gate[t * 2 + 0] = p[i0] / gsum;

        int pos1 = atomicAdd(&d_count[i1], 1);
        d_list[i1 * TOK + pos1] = (int)t;
        d_slot[t * 2 + 1] = i1 * TOK + pos1;
        d_gate[t * 2 + 1] = p[i1] / gsum;
    }
}

__global__ __launch_bounds__(256) void combine_ln_kernel(
    const __half* __restrict__ Y, const __half* __restrict__ x1,
    const float* __restrict__ g, const float* __restrict__ bb,
    float* __restrict__ out)
{
    __shared__ float red[256];
    __shared__ int soff[NEXP];
    size_t t = blockIdx.x;
    int tid = threadIdx.x;
    if (tid == 0) {
        int a = 0;
#pragma unroll
        for (int e = 0; e < NEXP; e++) { soff[e] = a; a += d_count[e]; }
    }
    __syncthreads();
    int sl0 = d_slot[t * 2 + 0], sl1 = d_slot[t * 2 + 1];
    size_t r0 = (size_t)soff[sl0 / TOK] + (sl0 % TOK);
    size_t r1 = (size_t)soff[sl1 / TOK] + (sl1 % TOK);
    float g0 = d_gate[t * 2 + 0], g1 = d_gate[t * 2 + 1];
    float v[4];
    float s = 0.f;
#pragma unroll
    for (int i = 0; i < 4; i++) {
        int d = tid + i * 256;
        float y = g0 * __half2float(Y[r0 * DM + d]) + g1 * __half2float(Y[r1 * DM + d]);
        v[i] = __half2float(x1[t * DM + d]) + y;
        s += v[i];
    }
    float mu = blk_sum(s, red) * (1.0f / DM);
    float sq = 0.f;
#pragma unroll
    for (int i = 0; i < 4; i++) { float c = v[i] - mu; sq += c * c; }
    float var = blk_sum(sq, red) * (1.0f / DM);
    float rstd = rsqrtf(var + 1e-5f);
#pragma unroll
    for (int i = 0; i < 4; i++) {
        int d = tid + i * 256;
        out[t * DM + d] = (v[i] - mu) * rstd * g[d] + bb[d];
    }
}

// ============================ launch ============================
extern "C" void kernel_launch(void* const* d_in, const int* in_sizes, int n_in,
                              void* d_out, int out_size)
{
    const float* src   = (const float*)d_in[0];
    const float* in_w  = (const float*)d_in[1];
    const float* in_b  = (const float*)d_in[2];
    const float* out_w = (const float*)d_in[3];
    const float* out_b = (const float*)d_in[4];
    const float* ln1g  = (const float*)d_in[5];
    const float* ln1b  = (const float*)d_in[6];
    const float* rw    = (const float*)d_in[7];
    const float* rb    = (const float*)d_in[8];
    const float* w1    = (const float*)d_in[9];
    const float* b1    = (const float*)d_in[10];
    const float* w2    = (const float*)d_in[11];
    const float* b2    = (const float*)d_in[12];
    const float* ln2g  = (const float*)d_in[13];
    const float* ln2b  = (const float*)d_in[14];
    float* out = (float*)d_out;

#define GETP(T, sym) ({ void* _p; cudaGetSymbolAddress(&_p, sym); (T*)_p; })
    __half* projh = GETP(__half, g_projh);
    __half* Yh    = GETP(__half, g_Yh);
    __half* qkvh  = GETP(__half, g_qkvh);
    __half* srch  = GETP(__half, g_srch);
    __half* attnh = GETP(__half, g_attnh);
    __half* wqkv  = GETP(__half, g_wqkv);
    __half* wo    = GETP(__half, g_wo);
    __half* x1h = GETP(__half, g_x1h);
    __half* w1h = GETP(__half, g_w1h);
    __half* w2h = GETP(__half, g_w2h);
    __half* Hh  = GETP(__half, g_Hh);
    int* cnt  = GETP(int, d_count);
    int* list = GETP(int, d_list);

    static cudaStream_t s_side = nullptr;
    static cudaEvent_t ev_fork, ev_wo, ev_w1, ev_w2;
    static bool attr_done = false;
    if (!attr_done) {
        cudaFuncSetAttribute((hgemm<1,1>), cudaFuncAttributeMaxDynamicSharedMemorySize, HGEMM_SMEM);
        cudaFuncSetAttribute((hgemm<2,1>), cudaFuncAttributeMaxDynamicSharedMemorySize, HGEMM_SMEM);
        cudaFuncSetAttribute((hgemm<3,0>), cudaFuncAttributeMaxDynamicSharedMemorySize, HGEMM_SMEM);
        cudaFuncSetAttribute(fa_kernel, cudaFuncAttributeMaxDynamicSharedMemorySize, FA_SMEM);
        cudaStreamCreateWithFlags(&s_side, cudaStreamNonBlocking);
        cudaEventCreateWithFlags(&ev_fork, cudaEventDisableTiming);
        cudaEventCreateWithFlags(&ev_wo, cudaEventDisableTiming);
        cudaEventCreateWithFlags(&ev_w1, cudaEventDisableTiming);
        cudaEventCreateWithFlags(&ev_w2, cudaEventDisableTiming);
        attr_done = true;
    }

    init_kernel<<<1, 32>>>();

    // fused conversion: src + wqkv in one launch
    {
        int n4a = TOK * DM / 4, n4b = D3 * DM / 4;
        cvt2_h_kernel<<<(n4a + n4b + 255) / 256, 256>>>(src, srch, n4a, in_w, wqkv, n4b);
    }

    // side stream: straight fp16 copies
    cudaEventRecord(ev_fork, 0);
    cudaStreamWaitEvent(s_side, ev_fork, 0);
    cvt_h_kernel<<<(DM * DM / 4 + 255) / 256, 256, 0, s_side>>>(out_w, wo, DM * DM / 4);
    cudaEventRecord(ev_wo, s_side);
    cvt_h_kernel<<<(NEXP * DM * DFF / 4 + 255) / 256, 256, 0, s_side>>>(w1, w1h, NEXP * DM * DFF / 4);
    cudaEventRecord(ev_w1, s_side);
    cvt_h_kernel<<<(NEXP * DFF * DM / 4 + 255) / 256, 256, 0, s_side>>>(w2, w2h, NEXP * DFF * DM / 4);
    cudaEventRecord(ev_w2, s_side);

    // QKV = src @ in_w^T + b  (fp16 out, B = [N,K])
    hgemm<3,0><<<dim3(D3 / BN, TOK / BM), 256, HGEMM_SMEM>>>(
        srch, wqkv, in_b, qkvh, nullptr, nullptr, TOK, D3, DM);

    // flash attention (64 q-rows/block, single buffer — proven config)
    fa_kernel<<<dim3(NB * NHEAD, SEQ / 64), 128, FA_SMEM>>>(qkvh, attnh);

    // proj = attn @ out_w^T + b  (fp16 out, B = [N,K])
    cudaStreamWaitEvent(0, ev_wo, 0);
    hgemm<3,0><<<dim3(DM / BN, TOK / BM), 256, HGEMM_SMEM>>>(
        attnh, wo, out_b, projh, nullptr, nullptr, TOK, DM, DM);

    // x1 = LN(src + proj) + fused router
    add_ln_router_kernel<<<TOK, 256>>>(src, projh, ln1g, ln1b, rw, rb, x1h);

    // H = relu(gather(x1) @ w1 + b1)  (offsets computed in-kernel)
    cudaStreamWaitEvent(0, ev_w1, 0);
    hgemm<1,1><<<dim3(DFF / BN, TOK / BM, NEXP), 256, HGEMM_SMEM>>>(
        x1h, w1h, b1, Hh, cnt, list, 0, DFF, DM);
    // Y = H @ w2 + b2
    cudaStreamWaitEvent(0, ev_w2, 0);
    hgemm<2,1><<<dim3(DM / BN, TOK / BM, NEXP), 256, HGEMM_SMEM>>>(
        Hh, w2h, b2, Yh, cnt, nullptr, 0, DM, DFF);

    combine_ln_kernel<<<TOK, 256>>>(Yh, x1h, ln2g, ln2b, out);
    lb_kernel<<<1, 32>>>(out, out_size);
}